// round 1
// baseline (speedup 1.0000x reference)
#include <cuda_runtime.h>
#include <cuda_bf16.h>
#include <cstdint>

#define D 128
#define BM 64
#define EPS 1e-5f

// Scratch (no cudaMalloc allowed): two N x D fp32 buffers + BN stats.
__device__ float g_Z[12800000];
__device__ float g_A[12800000];
__device__ float g_sum[D];
__device__ float g_sumsq[D];
__device__ float g_scale[D];
__device__ float g_shift[D];

// ---------------------------------------------------------------------------
// GEMM: out[N,128] = act(H)[N,128] @ W[128,128] + b
// act (optional): per-column BN affine + ReLU applied while staging H to smem.
// Block: 256 threads, computes BM=64 rows x 128 cols.
// smem: W (64KB) + H tile (32KB) = 96KB dynamic.
// ---------------------------------------------------------------------------
__global__ __launch_bounds__(256) void gemm_kernel(
    const float* __restrict__ H, const float* __restrict__ W,
    const float* __restrict__ bias,
    const float* __restrict__ scale, const float* __restrict__ shift,
    float* __restrict__ out, int N, int use_act)
{
    extern __shared__ float sm[];
    float* sW = sm;              // 128*128
    float* sH = sm + D * D;      // BM*128

    int tid = threadIdx.x;

    // Stage W: 4096 float4, 16 per thread.
    const float4* Wv = (const float4*)W;
    float4* sWv = (float4*)sW;
#pragma unroll
    for (int i = 0; i < 16; i++) sWv[tid + 256 * i] = Wv[tid + 256 * i];

    // Stage H tile (with fused BN+ReLU): 2048 float4, 8 per thread.
    int row0 = blockIdx.x * BM;
    const float4* Hv = (const float4*)(H + (size_t)row0 * D);
    float4* sHv = (float4*)sH;
#pragma unroll
    for (int i = 0; i < (BM * D / 4) / 256; i++) {
        int idx = tid + 256 * i;          // float4 index within tile
        int r = idx >> 5;                 // 32 float4 per row
        float4 v;
        if (row0 + r < N) v = Hv[idx];
        else              v = make_float4(0.f, 0.f, 0.f, 0.f);
        if (use_act) {
            int c = (idx & 31) * 4;
            v.x = fmaxf(fmaf(v.x, scale[c + 0], shift[c + 0]), 0.f);
            v.y = fmaxf(fmaf(v.y, scale[c + 1], shift[c + 1]), 0.f);
            v.z = fmaxf(fmaf(v.z, scale[c + 2], shift[c + 2]), 0.f);
            v.w = fmaxf(fmaf(v.w, scale[c + 3], shift[c + 3]), 0.f);
        }
        sHv[idx] = v;
    }
    __syncthreads();

    int warp = tid >> 5, lane = tid & 31;
    int rbase = warp * 8;       // 8 rows per thread
    int cbase = lane * 4;       // 4 cols per thread

    float acc[8][4] = {};
#pragma unroll 4
    for (int k = 0; k < D; k++) {
        float4 wv = *(const float4*)(sW + k * D + cbase);
#pragma unroll
        for (int r = 0; r < 8; r++) {
            float h = sH[(rbase + r) * D + k];   // warp-broadcast LDS
            acc[r][0] = fmaf(h, wv.x, acc[r][0]);
            acc[r][1] = fmaf(h, wv.y, acc[r][1]);
            acc[r][2] = fmaf(h, wv.z, acc[r][2]);
            acc[r][3] = fmaf(h, wv.w, acc[r][3]);
        }
    }

    float4 bv = *(const float4*)(bias + cbase);
#pragma unroll
    for (int r = 0; r < 8; r++) {
        int gr = row0 + rbase + r;
        if (gr < N) {
            float4 o;
            o.x = acc[r][0] + bv.x;
            o.y = acc[r][1] + bv.y;
            o.z = acc[r][2] + bv.z;
            o.w = acc[r][3] + bv.w;
            *(float4*)(out + (size_t)gr * D + cbase) = o;
        }
    }
}

// ---------------------------------------------------------------------------
// SpMM scatter: out[row[e]] += w[e] * H[col[e]]  (vector f32 atomics, sm_90+)
// One warp per edge; each lane handles 4 consecutive features.
// ---------------------------------------------------------------------------
__global__ __launch_bounds__(256) void spmm_kernel(
    const float* __restrict__ H, const float* __restrict__ ew,
    const int* __restrict__ row, const int* __restrict__ col,
    float* __restrict__ out, int E)
{
    int e = blockIdx.x * 8 + (threadIdx.x >> 5);
    if (e >= E) return;
    int lane = threadIdx.x & 31;
    int r = __ldg(&row[e]);
    int c = __ldg(&col[e]);
    float w = __ldg(&ew[e]);
    float4 v = ((const float4*)(H + (size_t)c * D))[lane];
    v.x *= w; v.y *= w; v.z *= w; v.w *= w;
    float* dst = out + (size_t)r * D + lane * 4;
    asm volatile("red.global.add.v4.f32 [%0], {%1,%2,%3,%4};"
                 :: "l"(dst), "f"(v.x), "f"(v.y), "f"(v.z), "f"(v.w)
                 : "memory");
}

// ---------------------------------------------------------------------------
// BN column statistics: per-block partial sum/sumsq over a row chunk,
// combined via fp32 atomics. 128 threads = 1 per feature column.
// ---------------------------------------------------------------------------
#define RPB 256
__global__ __launch_bounds__(128) void bn_stats_kernel(
    const float* __restrict__ A, float* __restrict__ sum,
    float* __restrict__ sumsq, int N)
{
    int d = threadIdx.x;
    int r0 = blockIdx.x * RPB;
    int rend = min(r0 + RPB, N);
    float s = 0.f, q = 0.f;
    for (int r = r0; r < rend; r++) {
        float v = A[(size_t)r * D + d];
        s += v;
        q = fmaf(v, v, q);
    }
    atomicAdd(&sum[d], s);
    atomicAdd(&sumsq[d], q);
}

__global__ void bn_finalize_kernel(
    const float* __restrict__ sum, const float* __restrict__ sumsq,
    const float* __restrict__ g, const float* __restrict__ be,
    float* __restrict__ scale, float* __restrict__ shift, float invN)
{
    int d = threadIdx.x;
    float m = sum[d] * invN;
    float v = sumsq[d] * invN - m * m;
    float sc = g[d] * rsqrtf(v + EPS);
    scale[d] = sc;
    shift[d] = be[d] - m * sc;
}

// ---------------------------------------------------------------------------
// Pipeline:
//   z0 = x@W0+b0 ; a0 = A z0 ; bn0 stats
//   z1 = relu(bn(a0))@W1+b1 (fused) ; a1 = A z1 ; bn1 stats
//   z2 = relu(bn(a1))@W2+b2 (fused) ; out = A z2
// ---------------------------------------------------------------------------
extern "C" void kernel_launch(void* const* d_in, const int* in_sizes, int n_in,
                              void* d_out, int out_size)
{
    const float* x   = (const float*)d_in[0];
    const float* ew  = (const float*)d_in[1];
    const float* W0  = (const float*)d_in[2];
    const float* b0  = (const float*)d_in[3];
    const float* g0  = (const float*)d_in[4];
    const float* be0 = (const float*)d_in[5];
    const float* W1  = (const float*)d_in[6];
    const float* b1  = (const float*)d_in[7];
    const float* g1  = (const float*)d_in[8];
    const float* be1 = (const float*)d_in[9];
    const float* W2  = (const float*)d_in[10];
    const float* b2  = (const float*)d_in[11];
    const int*   row = (const int*)d_in[12];
    const int*   col = (const int*)d_in[13];
    float* out = (float*)d_out;

    int N = in_sizes[0] / D;
    int E = in_sizes[1];

    float *Z, *A, *Sum, *Sumsq, *Scale, *Shift;
    cudaGetSymbolAddress((void**)&Z, g_Z);
    cudaGetSymbolAddress((void**)&A, g_A);
    cudaGetSymbolAddress((void**)&Sum, g_sum);
    cudaGetSymbolAddress((void**)&Sumsq, g_sumsq);
    cudaGetSymbolAddress((void**)&Scale, g_scale);
    cudaGetSymbolAddress((void**)&Shift, g_shift);

    size_t smem = (size_t)(D * D + BM * D) * sizeof(float);  // 96 KB
    cudaFuncSetAttribute(gemm_kernel, cudaFuncAttributeMaxDynamicSharedMemorySize,
                         (int)smem);

    int gemmGrid  = (N + BM - 1) / BM;
    int spmmGrid  = (E + 7) / 8;
    int statsGrid = (N + RPB - 1) / RPB;
    size_t featBytes = (size_t)N * D * sizeof(float);
    float invN = 1.0f / (float)N;

    // ---- layer 0 ----
    gemm_kernel<<<gemmGrid, 256, smem>>>(x, W0, b0, nullptr, nullptr, Z, N, 0);
    cudaMemsetAsync(A, 0, featBytes);
    spmm_kernel<<<spmmGrid, 256>>>(Z, ew, row, col, A, E);
    cudaMemsetAsync(Sum, 0, D * sizeof(float));
    cudaMemsetAsync(Sumsq, 0, D * sizeof(float));
    bn_stats_kernel<<<statsGrid, 128>>>(A, Sum, Sumsq, N);
    bn_finalize_kernel<<<1, 128>>>(Sum, Sumsq, g0, be0, Scale, Shift, invN);

    // ---- layer 1 (BN+ReLU fused into GEMM load) ----
    gemm_kernel<<<gemmGrid, 256, smem>>>(A, W1, b1, Scale, Shift, Z, N, 1);
    cudaMemsetAsync(A, 0, featBytes);
    spmm_kernel<<<spmmGrid, 256>>>(Z, ew, row, col, A, E);
    cudaMemsetAsync(Sum, 0, D * sizeof(float));
    cudaMemsetAsync(Sumsq, 0, D * sizeof(float));
    bn_stats_kernel<<<statsGrid, 128>>>(A, Sum, Sumsq, N);
    bn_finalize_kernel<<<1, 128>>>(Sum, Sumsq, g1, be1, Scale, Shift, invN);

    // ---- layer 2 (final, no BN on output) ----
    gemm_kernel<<<gemmGrid, 256, smem>>>(A, W2, b2, Scale, Shift, Z, N, 1);
    cudaMemsetAsync(out, 0, (size_t)out_size * sizeof(float));
    spmm_kernel<<<spmmGrid, 256>>>(Z, ew, row, col, out, E);
}

// round 2
// speedup vs baseline: 1.1614x; 1.1614x over previous
#include <cuda_runtime.h>
#include <cuda_bf16.h>
#include <cstdint>

#define D 128
#define BM 64
#define EPS 1e-5f
#define MAXN 100000
#define MAXE 1600000

// Scratch (no cudaMalloc allowed)
__device__ float g_Z[12800000];        // N x D
__device__ float g_A[12800000];        // N x D
__device__ float g_sum[D];
__device__ float g_sumsq[D];
__device__ float g_scale[D];
__device__ float g_shift[D];
__device__ int   g_deg[MAXN];
__device__ int   g_rowptr[MAXN + 1];
__device__ int   g_cursor[MAXN];
__device__ int   g_ecol[MAXE];
__device__ float g_ew2[MAXE];
__device__ int   g_blksum[1024];

// ---------------------------------------------------------------------------
// GEMM: out[N,128] = act(H)[N,128] @ W[128,128] + b
// act: per-column BN affine + ReLU fused into smem staging of H.
// ---------------------------------------------------------------------------
__global__ __launch_bounds__(256) void gemm_kernel(
    const float* __restrict__ H, const float* __restrict__ W,
    const float* __restrict__ bias,
    const float* __restrict__ scale, const float* __restrict__ shift,
    float* __restrict__ out, int N, int use_act)
{
    extern __shared__ float sm[];
    float* sW = sm;              // 128*128
    float* sH = sm + D * D;      // BM*128

    int tid = threadIdx.x;

    const float4* Wv = (const float4*)W;
    float4* sWv = (float4*)sW;
#pragma unroll
    for (int i = 0; i < 16; i++) sWv[tid + 256 * i] = Wv[tid + 256 * i];

    int row0 = blockIdx.x * BM;
    const float4* Hv = (const float4*)(H + (size_t)row0 * D);
    float4* sHv = (float4*)sH;
#pragma unroll
    for (int i = 0; i < (BM * D / 4) / 256; i++) {
        int idx = tid + 256 * i;
        int r = idx >> 5;
        float4 v;
        if (row0 + r < N) v = Hv[idx];
        else              v = make_float4(0.f, 0.f, 0.f, 0.f);
        if (use_act) {
            int c = (idx & 31) * 4;
            v.x = fmaxf(fmaf(v.x, scale[c + 0], shift[c + 0]), 0.f);
            v.y = fmaxf(fmaf(v.y, scale[c + 1], shift[c + 1]), 0.f);
            v.z = fmaxf(fmaf(v.z, scale[c + 2], shift[c + 2]), 0.f);
            v.w = fmaxf(fmaf(v.w, scale[c + 3], shift[c + 3]), 0.f);
        }
        sHv[idx] = v;
    }
    __syncthreads();

    int warp = tid >> 5, lane = tid & 31;
    int rbase = warp * 8;
    int cbase = lane * 4;

    float acc[8][4] = {};
#pragma unroll 4
    for (int k = 0; k < D; k++) {
        float4 wv = *(const float4*)(sW + k * D + cbase);
#pragma unroll
        for (int r = 0; r < 8; r++) {
            float h = sH[(rbase + r) * D + k];
            acc[r][0] = fmaf(h, wv.x, acc[r][0]);
            acc[r][1] = fmaf(h, wv.y, acc[r][1]);
            acc[r][2] = fmaf(h, wv.z, acc[r][2]);
            acc[r][3] = fmaf(h, wv.w, acc[r][3]);
        }
    }

    float4 bv = *(const float4*)(bias + cbase);
#pragma unroll
    for (int r = 0; r < 8; r++) {
        int gr = row0 + rbase + r;
        if (gr < N) {
            float4 o;
            o.x = acc[r][0] + bv.x;
            o.y = acc[r][1] + bv.y;
            o.z = acc[r][2] + bv.z;
            o.w = acc[r][3] + bv.w;
            *(float4*)(out + (size_t)gr * D + cbase) = o;
        }
    }
}

// ---------------------------------------------------------------------------
// CSR build
// ---------------------------------------------------------------------------
__global__ void hist_kernel(const int* __restrict__ row, int* __restrict__ deg, int E)
{
    int e = blockIdx.x * blockDim.x + threadIdx.x;
    if (e < E) atomicAdd(&deg[row[e]], 1);
}

__global__ __launch_bounds__(1024) void blocksum_kernel(
    const int* __restrict__ deg, int* __restrict__ blksum, int N)
{
    int i = blockIdx.x * 1024 + threadIdx.x;
    int v = (i < N) ? deg[i] : 0;
#pragma unroll
    for (int off = 16; off > 0; off >>= 1) v += __shfl_down_sync(0xffffffffu, v, off);
    __shared__ int sm[32];
    int lane = threadIdx.x & 31, wid = threadIdx.x >> 5;
    if (lane == 0) sm[wid] = v;
    __syncthreads();
    if (wid == 0) {
        v = sm[lane];
#pragma unroll
        for (int off = 16; off > 0; off >>= 1) v += __shfl_down_sync(0xffffffffu, v, off);
        if (lane == 0) blksum[blockIdx.x] = v;
    }
}

__global__ __launch_bounds__(1024) void scanpart_kernel(int* __restrict__ blksum, int nb)
{
    __shared__ int sm[1024];
    int tid = threadIdx.x;
    sm[tid] = (tid < nb) ? blksum[tid] : 0;
    __syncthreads();
    if (tid == 0) {
        int run = 0;
        for (int i = 0; i < nb; i++) { int t = sm[i]; sm[i] = run; run += t; }
    }
    __syncthreads();
    if (tid < nb) blksum[tid] = sm[tid];
}

__global__ __launch_bounds__(1024) void rowptr_kernel(
    const int* __restrict__ deg, const int* __restrict__ blksum,
    int* __restrict__ rowptr, int N)
{
    int i = blockIdx.x * 1024 + threadIdx.x;
    int v = (i < N) ? deg[i] : 0;
    int lane = threadIdx.x & 31, wid = threadIdx.x >> 5;
    int incl = v;
#pragma unroll
    for (int off = 1; off < 32; off <<= 1) {
        int t = __shfl_up_sync(0xffffffffu, incl, off);
        if (lane >= off) incl += t;
    }
    __shared__ int wsum[32];
    if (lane == 31) wsum[wid] = incl;
    __syncthreads();
    if (wid == 0) {
        int w = wsum[lane];
#pragma unroll
        for (int off = 1; off < 32; off <<= 1) {
            int t = __shfl_up_sync(0xffffffffu, w, off);
            if (lane >= off) w += t;
        }
        wsum[lane] = w;
    }
    __syncthreads();
    int offset = blksum[blockIdx.x] + (wid > 0 ? wsum[wid - 1] : 0);
    int excl = offset + incl - v;
    if (i < N) rowptr[i] = excl;
    if (i == N - 1) rowptr[N] = excl + v;
}

__global__ void scatter_kernel(
    const int* __restrict__ row, const int* __restrict__ col,
    const float* __restrict__ ew, int* __restrict__ cursor,
    int* __restrict__ ecol, float* __restrict__ ew2, int E)
{
    int e = blockIdx.x * blockDim.x + threadIdx.x;
    if (e < E) {
        int p = atomicAdd(&cursor[row[e]], 1);
        ecol[p] = col[e];
        ew2[p]  = ew[e];
    }
}

// ---------------------------------------------------------------------------
// Gather SpMM: out[r] = sum_{e in row r} w_e * H[col_e].  One warp per row.
// ---------------------------------------------------------------------------
__global__ __launch_bounds__(256) void spmm_csr_kernel(
    const float* __restrict__ H, const int* __restrict__ rowptr,
    const int* __restrict__ ecol, const float* __restrict__ ew2,
    float* __restrict__ out, int N)
{
    int r = blockIdx.x * 8 + (threadIdx.x >> 5);
    if (r >= N) return;
    int lane = threadIdx.x & 31;
    int start = rowptr[r], end = rowptr[r + 1];

    float4 acc = make_float4(0.f, 0.f, 0.f, 0.f);
    const float4* Hv = (const float4*)H;

    for (int base = start; base < end; base += 32) {
        int e = base + lane;
        int c = 0; float w = 0.f;
        if (e < end) { c = ecol[e]; w = ew2[e]; }
        int cnt = min(32, end - base);
#pragma unroll 4
        for (int i = 0; i < cnt; i++) {
            int ci  = __shfl_sync(0xffffffffu, c, i);
            float wi = __shfl_sync(0xffffffffu, w, i);
            float4 v = Hv[(size_t)ci * 32 + lane];
            acc.x = fmaf(wi, v.x, acc.x);
            acc.y = fmaf(wi, v.y, acc.y);
            acc.z = fmaf(wi, v.z, acc.z);
            acc.w = fmaf(wi, v.w, acc.w);
        }
    }
    ((float4*)(out + (size_t)r * D))[lane] = acc;
}

// ---------------------------------------------------------------------------
// BN stats / finalize
// ---------------------------------------------------------------------------
#define RPB 256
__global__ __launch_bounds__(128) void bn_stats_kernel(
    const float* __restrict__ A, float* __restrict__ sum,
    float* __restrict__ sumsq, int N)
{
    int d = threadIdx.x;
    int r0 = blockIdx.x * RPB;
    int rend = min(r0 + RPB, N);
    float s = 0.f, q = 0.f;
    for (int r = r0; r < rend; r++) {
        float v = A[(size_t)r * D + d];
        s += v;
        q = fmaf(v, v, q);
    }
    atomicAdd(&sum[d], s);
    atomicAdd(&sumsq[d], q);
}

__global__ void bn_finalize_kernel(
    const float* __restrict__ sum, const float* __restrict__ sumsq,
    const float* __restrict__ g, const float* __restrict__ be,
    float* __restrict__ scale, float* __restrict__ shift, float invN)
{
    int d = threadIdx.x;
    float m = sum[d] * invN;
    float v = sumsq[d] * invN - m * m;
    float sc = g[d] * rsqrtf(v + EPS);
    scale[d] = sc;
    shift[d] = be[d] - m * sc;
}

// ---------------------------------------------------------------------------
extern "C" void kernel_launch(void* const* d_in, const int* in_sizes, int n_in,
                              void* d_out, int out_size)
{
    const float* x   = (const float*)d_in[0];
    const float* ew  = (const float*)d_in[1];
    const float* W0  = (const float*)d_in[2];
    const float* b0  = (const float*)d_in[3];
    const float* g0  = (const float*)d_in[4];
    const float* be0 = (const float*)d_in[5];
    const float* W1  = (const float*)d_in[6];
    const float* b1  = (const float*)d_in[7];
    const float* g1  = (const float*)d_in[8];
    const float* be1 = (const float*)d_in[9];
    const float* W2  = (const float*)d_in[10];
    const float* b2  = (const float*)d_in[11];
    const int*   row = (const int*)d_in[12];
    const int*   col = (const int*)d_in[13];
    float* out = (float*)d_out;

    int N = in_sizes[0] / D;
    int E = in_sizes[1];

    float *Z, *A, *Sum, *Sumsq, *Scale, *Shift, *Ew2;
    int *Deg, *Rowptr, *Cursor, *Ecol, *Blksum;
    cudaGetSymbolAddress((void**)&Z, g_Z);
    cudaGetSymbolAddress((void**)&A, g_A);
    cudaGetSymbolAddress((void**)&Sum, g_sum);
    cudaGetSymbolAddress((void**)&Sumsq, g_sumsq);
    cudaGetSymbolAddress((void**)&Scale, g_scale);
    cudaGetSymbolAddress((void**)&Shift, g_shift);
    cudaGetSymbolAddress((void**)&Deg, g_deg);
    cudaGetSymbolAddress((void**)&Rowptr, g_rowptr);
    cudaGetSymbolAddress((void**)&Cursor, g_cursor);
    cudaGetSymbolAddress((void**)&Ecol, g_ecol);
    cudaGetSymbolAddress((void**)&Ew2, g_ew2);
    cudaGetSymbolAddress((void**)&Blksum, g_blksum);

    size_t smem = (size_t)(D * D + BM * D) * sizeof(float);  // 96 KB
    cudaFuncSetAttribute(gemm_kernel, cudaFuncAttributeMaxDynamicSharedMemorySize,
                         (int)smem);

    int gemmGrid  = (N + BM - 1) / BM;
    int spmmGrid  = (N + 7) / 8;
    int statsGrid = (N + RPB - 1) / RPB;
    int nb        = (N + 1023) / 1024;
    float invN = 1.0f / (float)N;

    // ---- CSR build (amortized over 3 SpMMs) ----
    cudaMemsetAsync(Deg, 0, N * sizeof(int));
    hist_kernel<<<(E + 255) / 256, 256>>>(row, Deg, E);
    blocksum_kernel<<<nb, 1024>>>(Deg, Blksum, N);
    scanpart_kernel<<<1, 1024>>>(Blksum, nb);
    rowptr_kernel<<<nb, 1024>>>(Deg, Blksum, Rowptr, N);
    cudaMemcpyAsync(Cursor, Rowptr, N * sizeof(int), cudaMemcpyDeviceToDevice);
    scatter_kernel<<<(E + 255) / 256, 256>>>(row, col, ew, Cursor, Ecol, Ew2, E);

    // ---- layer 0 ----
    gemm_kernel<<<gemmGrid, 256, smem>>>(x, W0, b0, nullptr, nullptr, Z, N, 0);
    spmm_csr_kernel<<<spmmGrid, 256>>>(Z, Rowptr, Ecol, Ew2, A, N);
    cudaMemsetAsync(Sum, 0, D * sizeof(float));
    cudaMemsetAsync(Sumsq, 0, D * sizeof(float));
    bn_stats_kernel<<<statsGrid, 128>>>(A, Sum, Sumsq, N);
    bn_finalize_kernel<<<1, 128>>>(Sum, Sumsq, g0, be0, Scale, Shift, invN);

    // ---- layer 1 ----
    gemm_kernel<<<gemmGrid, 256, smem>>>(A, W1, b1, Scale, Shift, Z, N, 1);
    spmm_csr_kernel<<<spmmGrid, 256>>>(Z, Rowptr, Ecol, Ew2, A, N);
    cudaMemsetAsync(Sum, 0, D * sizeof(float));
    cudaMemsetAsync(Sumsq, 0, D * sizeof(float));
    bn_stats_kernel<<<statsGrid, 128>>>(A, Sum, Sumsq, N);
    bn_finalize_kernel<<<1, 128>>>(Sum, Sumsq, g1, be1, Scale, Shift, invN);

    // ---- layer 2 ----
    gemm_kernel<<<gemmGrid, 256, smem>>>(A, W2, b2, Scale, Shift, Z, N, 1);
    spmm_csr_kernel<<<spmmGrid, 256>>>(Z, Rowptr, Ecol, Ew2, out, N);
}

// round 4
// speedup vs baseline: 1.9942x; 1.7171x over previous
#include <cuda_runtime.h>
#include <cuda_bf16.h>
#include <cstdint>

#define D 128
#define EPS 1e-5f
#define MAXN 100000
#define MAXE 1600000
#define SA 136              // padded row stride (bf16 elems) for smem tiles
#define SA_W (SA / 2)       // 68 words

// ---------------- scratch (no cudaMalloc allowed) ----------------
__device__ float g_Z[12800000];        // N x D
__device__ float g_A[12800000];        // N x D
__device__ float g_sum[D];
__device__ float g_sumsq[D];
__device__ float g_scale[D];
__device__ float g_shift[D];
__device__ int   g_deg[MAXN];
__device__ int   g_rowptr[MAXN + 1];
__device__ int   g_cursor[MAXN];
__device__ int   g_ecol[MAXE];
__device__ float g_ew2[MAXE];
__device__ int   g_blksum[1024];
// padded W^T bf16 hi/lo images: 3 layers x [128][136]
__device__ __nv_bfloat16 g_Whi[3 * 128 * SA];
__device__ __nv_bfloat16 g_Wlo[3 * 128 * SA];

// ---------------- W prep: transpose + bf16 split into padded layout ----------------
__global__ void wprep_kernel(const float* __restrict__ W0, const float* __restrict__ W1,
                             const float* __restrict__ W2,
                             __nv_bfloat16* __restrict__ whi, __nv_bfloat16* __restrict__ wlo)
{
    const float* W = (blockIdx.x == 0) ? W0 : (blockIdx.x == 1) ? W1 : W2;
    __nv_bfloat16* hi = whi + blockIdx.x * 128 * SA;
    __nv_bfloat16* lo = wlo + blockIdx.x * 128 * SA;
    for (int idx = threadIdx.x; idx < 16384; idx += blockDim.x) {
        int k = idx >> 7, n = idx & 127;     // W[k][n] -> Wt[n][k]
        float w = W[idx];
        __nv_bfloat16 h = __float2bfloat16(w);
        __nv_bfloat16 l = __float2bfloat16(w - __bfloat162float(h));
        hi[n * SA + k] = h;
        lo[n * SA + k] = l;
    }
}

// ---------------- HMMA GEMM: out = act(H) @ W + b   (bf16x3, fp32 acc) ----------------
// block = 256 threads (8 warps), tile 64 rows x 128 cols.
// smem: Ahi, Alo [64][136] bf16 ; Whi, Wlo [128][136] bf16  = 104448 B
#define SM_AHI 0
#define SM_ALO 17408
#define SM_WHI 34816
#define SM_WLO 69632
#define SM_TOT 104448

__device__ __forceinline__ void mma_bf16(float* c, uint32_t a0, uint32_t a1,
                                         uint32_t a2, uint32_t a3,
                                         uint32_t b0, uint32_t b1)
{
    asm volatile(
        "mma.sync.aligned.m16n8k16.row.col.f32.bf16.bf16.f32 "
        "{%0,%1,%2,%3}, {%4,%5,%6,%7}, {%8,%9}, {%0,%1,%2,%3};"
        : "+f"(c[0]), "+f"(c[1]), "+f"(c[2]), "+f"(c[3])
        : "r"(a0), "r"(a1), "r"(a2), "r"(a3), "r"(b0), "r"(b1));
}

__global__ __launch_bounds__(256) void gemm_mma_kernel(
    const float* __restrict__ H,
    const __nv_bfloat16* __restrict__ whi, const __nv_bfloat16* __restrict__ wlo,
    const float* __restrict__ bias,
    const float* __restrict__ scale, const float* __restrict__ shift,
    float* __restrict__ out, int N, int use_act)
{
    extern __shared__ char sm[];
    int tid = threadIdx.x, wid = tid >> 5, lane = tid & 31;

    // stage W hi/lo (straight copy, already padded/transposed): 2176 float4 each
    {
        const float4* bh = (const float4*)whi;
        const float4* bl = (const float4*)wlo;
        float4* sh = (float4*)(sm + SM_WHI);
        float4* sl = (float4*)(sm + SM_WLO);
#pragma unroll
        for (int i = 0; i < 9; i++) {
            int idx = tid + 256 * i;
            if (idx < 2176) { sh[idx] = bh[idx]; sl[idx] = bl[idx]; }
        }
    }

    // stage A tile: load H rows, act, bf16 split, padded store
    int row0 = blockIdx.x * 64;
    {
        const float4* Hv = (const float4*)(H + (size_t)row0 * D);
#pragma unroll
        for (int i = 0; i < 8; i++) {
            int idx = tid + 256 * i;          // 2048 float4
            int r = idx >> 5;
            int c = (idx & 31) * 4;
            float4 v;
            if (row0 + r < N) v = Hv[idx];
            else              v = make_float4(0.f, 0.f, 0.f, 0.f);
            if (use_act) {
                float4 sc = *(const float4*)(scale + c);
                float4 sf = *(const float4*)(shift + c);
                v.x = fmaxf(fmaf(v.x, sc.x, sf.x), 0.f);
                v.y = fmaxf(fmaf(v.y, sc.y, sf.y), 0.f);
                v.z = fmaxf(fmaf(v.z, sc.z, sf.z), 0.f);
                v.w = fmaxf(fmaf(v.w, sc.w, sf.w), 0.f);
            }
            __nv_bfloat162 h01 = __floats2bfloat162_rn(v.x, v.y);
            __nv_bfloat162 h23 = __floats2bfloat162_rn(v.z, v.w);
            float2 hf01 = __bfloat1622float2(h01);
            float2 hf23 = __bfloat1622float2(h23);
            __nv_bfloat162 l01 = __floats2bfloat162_rn(v.x - hf01.x, v.y - hf01.y);
            __nv_bfloat162 l23 = __floats2bfloat162_rn(v.z - hf23.x, v.w - hf23.y);
            uint32_t w0 = (uint32_t)(r * SA_W + (c >> 1));   // word index, 8B aligned
            uint2 hh; hh.x = *(uint32_t*)&h01; hh.y = *(uint32_t*)&h23;
            uint2 ll; ll.x = *(uint32_t*)&l01; ll.y = *(uint32_t*)&l23;
            *(uint2*)(sm + SM_AHI + w0 * 4) = hh;
            *(uint2*)(sm + SM_ALO + w0 * 4) = ll;
        }
    }
    __syncthreads();

    const uint32_t* pAh = (const uint32_t*)(sm + SM_AHI);
    const uint32_t* pAl = (const uint32_t*)(sm + SM_ALO);
    const uint32_t* pBh = (const uint32_t*)(sm + SM_WHI);
    const uint32_t* pBl = (const uint32_t*)(sm + SM_WLO);

    int m0 = (wid & 3) * 16;      // row strip
    int n0 = (wid >> 2) * 64;     // col half
    int g = lane >> 2, q = lane & 3;

    float acc[8][4] = {};
#pragma unroll
    for (int k = 0; k < 8; k++) {
        int kb2 = k * 8;          // k*16 elems = 8 words
        int ai = (m0 + g) * SA_W + kb2 + q;
        uint32_t ah0 = pAh[ai],           ah1 = pAh[ai + 8 * SA_W];
        uint32_t ah2 = pAh[ai + 4],       ah3 = pAh[ai + 8 * SA_W + 4];
        uint32_t al0 = pAl[ai],           al1 = pAl[ai + 8 * SA_W];
        uint32_t al2 = pAl[ai + 4],       al3 = pAl[ai + 8 * SA_W + 4];
#pragma unroll
        for (int t = 0; t < 8; t++) {
            int bi = (n0 + t * 8 + g) * SA_W + kb2 + q;
            uint32_t bh0 = pBh[bi], bh1 = pBh[bi + 4];
            uint32_t bl0 = pBl[bi], bl1 = pBl[bi + 4];
            mma_bf16(acc[t], ah0, ah1, ah2, ah3, bh0, bh1);
            mma_bf16(acc[t], al0, al1, al2, al3, bh0, bh1);
            mma_bf16(acc[t], ah0, ah1, ah2, ah3, bl0, bl1);
        }
    }

    // epilogue: c0,c1 -> row m0+g ; c2,c3 -> row m0+g+8 ; cols n0+t*8+2q,+1
    int r0g = row0 + m0 + g;
#pragma unroll
    for (int t = 0; t < 8; t++) {
        int colp = n0 + t * 8 + q * 2;
        float2 bv = *(const float2*)(bias + colp);
        if (r0g < N) {
            float2 o; o.x = acc[t][0] + bv.x; o.y = acc[t][1] + bv.y;
            *(float2*)(out + (size_t)r0g * D + colp) = o;
        }
        if (r0g + 8 < N) {
            float2 o; o.x = acc[t][2] + bv.x; o.y = acc[t][3] + bv.y;
            *(float2*)(out + (size_t)(r0g + 8) * D + colp) = o;
        }
    }
}

// ---------------- CSR build ----------------
__global__ void hist_kernel(const int* __restrict__ row, int* __restrict__ deg, int E)
{
    int e = blockIdx.x * blockDim.x + threadIdx.x;
    if (e < E) atomicAdd(&deg[row[e]], 1);
}

__global__ __launch_bounds__(1024) void blocksum_kernel(
    const int* __restrict__ deg, int* __restrict__ blksum, int N)
{
    int i = blockIdx.x * 1024 + threadIdx.x;
    int v = (i < N) ? deg[i] : 0;
#pragma unroll
    for (int off = 16; off > 0; off >>= 1) v += __shfl_down_sync(0xffffffffu, v, off);
    __shared__ int smr[32];
    int lane = threadIdx.x & 31, wid = threadIdx.x >> 5;
    if (lane == 0) smr[wid] = v;
    __syncthreads();
    if (wid == 0) {
        v = smr[lane];
#pragma unroll
        for (int off = 16; off > 0; off >>= 1) v += __shfl_down_sync(0xffffffffu, v, off);
        if (lane == 0) blksum[blockIdx.x] = v;
    }
}

__global__ __launch_bounds__(1024) void scanpart_kernel(int* __restrict__ blksum, int nb)
{
    __shared__ int smr[1024];
    int tid = threadIdx.x;
    smr[tid] = (tid < nb) ? blksum[tid] : 0;
    __syncthreads();
    if (tid == 0) {
        int run = 0;
        for (int i = 0; i < nb; i++) { int t = smr[i]; smr[i] = run; run += t; }
    }
    __syncthreads();
    if (tid < nb) blksum[tid] = smr[tid];
}

__global__ __launch_bounds__(1024) void rowptr_kernel(
    const int* __restrict__ deg, const int* __restrict__ blksum,
    int* __restrict__ rowptr, int N)
{
    int i = blockIdx.x * 1024 + threadIdx.x;
    int v = (i < N) ? deg[i] : 0;
    int lane = threadIdx.x & 31, wid = threadIdx.x >> 5;
    int incl = v;
#pragma unroll
    for (int off = 1; off < 32; off <<= 1) {
        int t = __shfl_up_sync(0xffffffffu, incl, off);
        if (lane >= off) incl += t;
    }
    __shared__ int wsum[32];
    if (lane == 31) wsum[wid] = incl;
    __syncthreads();
    if (wid == 0) {
        int w = wsum[lane];
#pragma unroll
        for (int off = 1; off < 32; off <<= 1) {
            int t = __shfl_up_sync(0xffffffffu, w, off);
            if (lane >= off) w += t;
        }
        wsum[lane] = w;
    }
    __syncthreads();
    int offset = blksum[blockIdx.x] + (wid > 0 ? wsum[wid - 1] : 0);
    int excl = offset + incl - v;
    if (i < N) rowptr[i] = excl;
    if (i == N - 1) rowptr[N] = excl + v;
}

__global__ void scatter_kernel(
    const int* __restrict__ row, const int* __restrict__ col,
    const float* __restrict__ ew, int* __restrict__ cursor,
    int* __restrict__ ecol, float* __restrict__ ew2, int E)
{
    int e = blockIdx.x * blockDim.x + threadIdx.x;
    if (e < E) {
        int p = atomicAdd(&cursor[row[e]], 1);
        ecol[p] = col[e];
        ew2[p]  = ew[e];
    }
}

// ---------------- gather SpMM: one warp per row ----------------
__global__ __launch_bounds__(256) void spmm_csr_kernel(
    const float* __restrict__ H, const int* __restrict__ rowptr,
    const int* __restrict__ ecol, const float* __restrict__ ew2,
    float* __restrict__ out, int N)
{
    int r = blockIdx.x * 8 + (threadIdx.x >> 5);
    if (r >= N) return;
    int lane = threadIdx.x & 31;
    int start = rowptr[r], end = rowptr[r + 1];

    float4 acc = make_float4(0.f, 0.f, 0.f, 0.f);
    const float4* Hv = (const float4*)H;

    for (int base = start; base < end; base += 32) {
        int e = base + lane;
        int c = 0; float w = 0.f;
        if (e < end) { c = ecol[e]; w = ew2[e]; }
        int cnt = min(32, end - base);
#pragma unroll 4
        for (int i = 0; i < cnt; i++) {
            int ci  = __shfl_sync(0xffffffffu, c, i);
            float wi = __shfl_sync(0xffffffffu, w, i);
            float4 v = Hv[(size_t)ci * 32 + lane];
            acc.x = fmaf(wi, v.x, acc.x);
            acc.y = fmaf(wi, v.y, acc.y);
            acc.z = fmaf(wi, v.z, acc.z);
            acc.w = fmaf(wi, v.w, acc.w);
        }
    }
    ((float4*)(out + (size_t)r * D))[lane] = acc;
}

// ---------------- BN ----------------
#define RPB 256
__global__ __launch_bounds__(128) void bn_stats_kernel(
    const float* __restrict__ A, float* __restrict__ sum,
    float* __restrict__ sumsq, int N)
{
    int d = threadIdx.x;
    int r0 = blockIdx.x * RPB;
    int rend = min(r0 + RPB, N);
    float s = 0.f, q = 0.f;
    for (int r = r0; r < rend; r++) {
        float v = A[(size_t)r * D + d];
        s += v;
        q = fmaf(v, v, q);
    }
    atomicAdd(&sum[d], s);
    atomicAdd(&sumsq[d], q);
}

__global__ void bn_finalize_kernel(
    const float* __restrict__ sum, const float* __restrict__ sumsq,
    const float* __restrict__ g, const float* __restrict__ be,
    float* __restrict__ scale, float* __restrict__ shift, float invN)
{
    int d = threadIdx.x;
    float m = sum[d] * invN;
    float v = sumsq[d] * invN - m * m;
    float sc = g[d] * rsqrtf(v + EPS);
    scale[d] = sc;
    shift[d] = be[d] - m * sc;
}

// ---------------------------------------------------------------------------
extern "C" void kernel_launch(void* const* d_in, const int* in_sizes, int n_in,
                              void* d_out, int out_size)
{
    const float* x   = (const float*)d_in[0];
    const float* ew  = (const float*)d_in[1];
    const float* W0  = (const float*)d_in[2];
    const float* b0  = (const float*)d_in[3];
    const float* g0  = (const float*)d_in[4];
    const float* be0 = (const float*)d_in[5];
    const float* W1  = (const float*)d_in[6];
    const float* b1  = (const float*)d_in[7];
    const float* g1  = (const float*)d_in[8];
    const float* be1 = (const float*)d_in[9];
    const float* W2  = (const float*)d_in[10];
    const float* b2  = (const float*)d_in[11];
    const int*   row = (const int*)d_in[12];
    const int*   col = (const int*)d_in[13];
    float* out = (float*)d_out;

    int N = in_sizes[0] / D;
    int E = in_sizes[1];

    float *Z, *A, *Sum, *Sumsq, *Scale, *Shift, *Ew2;
    int *Deg, *Rowptr, *Cursor, *Ecol, *Blksum;
    __nv_bfloat16 *Whi, *Wlo;
    cudaGetSymbolAddress((void**)&Z, g_Z);
    cudaGetSymbolAddress((void**)&A, g_A);
    cudaGetSymbolAddress((void**)&Sum, g_sum);
    cudaGetSymbolAddress((void**)&Sumsq, g_sumsq);
    cudaGetSymbolAddress((void**)&Scale, g_scale);
    cudaGetSymbolAddress((void**)&Shift, g_shift);
    cudaGetSymbolAddress((void**)&Deg, g_deg);
    cudaGetSymbolAddress((void**)&Rowptr, g_rowptr);
    cudaGetSymbolAddress((void**)&Cursor, g_cursor);
    cudaGetSymbolAddress((void**)&Ecol, g_ecol);
    cudaGetSymbolAddress((void**)&Ew2, g_ew2);
    cudaGetSymbolAddress((void**)&Blksum, g_blksum);
    cudaGetSymbolAddress((void**)&Whi, g_Whi);
    cudaGetSymbolAddress((void**)&Wlo, g_Wlo);

    cudaFuncSetAttribute(gemm_mma_kernel, cudaFuncAttributeMaxDynamicSharedMemorySize, SM_TOT);

    int gemmGrid  = (N + 63) / 64;
    int spmmGrid  = (N + 7) / 8;
    int statsGrid = (N + RPB - 1) / RPB;
    int nb        = (N + 1023) / 1024;
    float invN = 1.0f / (float)N;

    // ---- W prep + CSR build ----
    wprep_kernel<<<3, 256>>>(W0, W1, W2, Whi, Wlo);
    cudaMemsetAsync(Deg, 0, N * sizeof(int));
    hist_kernel<<<(E + 255) / 256, 256>>>(row, Deg, E);
    blocksum_kernel<<<nb, 1024>>>(Deg, Blksum, N);
    scanpart_kernel<<<1, 1024>>>(Blksum, nb);
    rowptr_kernel<<<nb, 1024>>>(Deg, Blksum, Rowptr, N);
    cudaMemcpyAsync(Cursor, Rowptr, N * sizeof(int), cudaMemcpyDeviceToDevice);
    scatter_kernel<<<(E + 255) / 256, 256>>>(row, col, ew, Cursor, Ecol, Ew2, E);

    // ---- layer 0 ----
    gemm_mma_kernel<<<gemmGrid, 256, SM_TOT>>>(x, Whi, Wlo, b0, nullptr, nullptr, Z, N, 0);
    spmm_csr_kernel<<<spmmGrid, 256>>>(Z, Rowptr, Ecol, Ew2, A, N);
    cudaMemsetAsync(Sum, 0, D * sizeof(float));
    cudaMemsetAsync(Sumsq, 0, D * sizeof(float));
    bn_stats_kernel<<<statsGrid, 128>>>(A, Sum, Sumsq, N);
    bn_finalize_kernel<<<1, 128>>>(Sum, Sumsq, g0, be0, Scale, Shift, invN);

    // ---- layer 1 ----
    gemm_mma_kernel<<<gemmGrid, 256, SM_TOT>>>(A, Whi + 128 * SA, Wlo + 128 * SA, b1,
                                               Scale, Shift, Z, N, 1);
    spmm_csr_kernel<<<spmmGrid, 256>>>(Z, Rowptr, Ecol, Ew2, A, N);
    cudaMemsetAsync(Sum, 0, D * sizeof(float));
    cudaMemsetAsync(Sumsq, 0, D * sizeof(float));
    bn_stats_kernel<<<statsGrid, 128>>>(A, Sum, Sumsq, N);
    bn_finalize_kernel<<<1, 128>>>(Sum, Sumsq, g1, be1, Scale, Shift, invN);

    // ---- layer 2 ----
    gemm_mma_kernel<<<gemmGrid, 256, SM_TOT>>>(A, Whi + 256 * SA, Wlo + 256 * SA, b2,
                                               Scale, Shift, Z, N, 1);
    spmm_csr_kernel<<<spmmGrid, 256>>>(Z, Rowptr, Ecol, Ew2, out, N);
}

// round 5
// speedup vs baseline: 2.1253x; 1.0657x over previous
#include <cuda_runtime.h>
#include <cuda_bf16.h>
#include <cuda_fp16.h>
#include <cstdint>

#define D 128
#define EPS 1e-5f
#define MAXN 100000
#define MAXE 1600000
#define SA 136              // padded row stride (bf16 elems) for smem tiles
#define SA_W (SA / 2)       // 68 words

// ---------------- scratch (no cudaMalloc allowed) ----------------
__device__ __half g_Z[12800000];       // N x D fp16 (GEMM out / SpMM in)
__device__ float  g_A[12800000];       // N x D fp32 (SpMM out / BN+GEMM in)
__device__ float g_sum[D];
__device__ float g_sumsq[D];
__device__ float g_scale[D];
__device__ float g_shift[D];
__device__ int   g_deg[MAXN];
__device__ int   g_rowptr[MAXN + 1];
__device__ int   g_cursor[MAXN];
__device__ int   g_ecol[MAXE];
__device__ float g_ew2[MAXE];
__device__ int   g_blksum[1024];
// padded W^T bf16 hi/lo images: 3 layers x [128][136]
__device__ __nv_bfloat16 g_Whi[3 * 128 * SA];
__device__ __nv_bfloat16 g_Wlo[3 * 128 * SA];

// ---------------- W prep: transpose + bf16 split into padded layout ----------------
__global__ void wprep_kernel(const float* __restrict__ W0, const float* __restrict__ W1,
                             const float* __restrict__ W2,
                             __nv_bfloat16* __restrict__ whi, __nv_bfloat16* __restrict__ wlo)
{
    const float* W = (blockIdx.x == 0) ? W0 : (blockIdx.x == 1) ? W1 : W2;
    __nv_bfloat16* hi = whi + blockIdx.x * 128 * SA;
    __nv_bfloat16* lo = wlo + blockIdx.x * 128 * SA;
    for (int idx = threadIdx.x; idx < 16384; idx += blockDim.x) {
        int k = idx >> 7, n = idx & 127;     // W[k][n] -> Wt[n][k]
        float w = W[idx];
        __nv_bfloat16 h = __float2bfloat16(w);
        __nv_bfloat16 l = __float2bfloat16(w - __bfloat162float(h));
        hi[n * SA + k] = h;
        lo[n * SA + k] = l;
    }
}

// ---------------- HMMA GEMM: Z(fp16) = act(H) @ W + b   (bf16x3, fp32 acc) ----------------
#define SM_AHI 0
#define SM_ALO 17408
#define SM_WHI 34816
#define SM_WLO 69632
#define SM_TOT 104448

__device__ __forceinline__ void mma_bf16(float* c, uint32_t a0, uint32_t a1,
                                         uint32_t a2, uint32_t a3,
                                         uint32_t b0, uint32_t b1)
{
    asm volatile(
        "mma.sync.aligned.m16n8k16.row.col.f32.bf16.bf16.f32 "
        "{%0,%1,%2,%3}, {%4,%5,%6,%7}, {%8,%9}, {%0,%1,%2,%3};"
        : "+f"(c[0]), "+f"(c[1]), "+f"(c[2]), "+f"(c[3])
        : "r"(a0), "r"(a1), "r"(a2), "r"(a3), "r"(b0), "r"(b1));
}

__global__ __launch_bounds__(256) void gemm_mma_kernel(
    const float* __restrict__ H,
    const __nv_bfloat16* __restrict__ whi, const __nv_bfloat16* __restrict__ wlo,
    const float* __restrict__ bias,
    const float* __restrict__ scale, const float* __restrict__ shift,
    __half* __restrict__ out, int N, int use_act)
{
    extern __shared__ char sm[];
    int tid = threadIdx.x, wid = tid >> 5, lane = tid & 31;

    // stage W hi/lo (straight copy, already padded/transposed): 2176 float4 each
    {
        const float4* bh = (const float4*)whi;
        const float4* bl = (const float4*)wlo;
        float4* sh = (float4*)(sm + SM_WHI);
        float4* sl = (float4*)(sm + SM_WLO);
#pragma unroll
        for (int i = 0; i < 9; i++) {
            int idx = tid + 256 * i;
            if (idx < 2176) { sh[idx] = bh[idx]; sl[idx] = bl[idx]; }
        }
    }

    // stage A tile: load H rows, act, bf16 split, padded store
    int row0 = blockIdx.x * 64;
    {
        const float4* Hv = (const float4*)(H + (size_t)row0 * D);
#pragma unroll
        for (int i = 0; i < 8; i++) {
            int idx = tid + 256 * i;          // 2048 float4
            int r = idx >> 5;
            int c = (idx & 31) * 4;
            float4 v;
            if (row0 + r < N) v = Hv[idx];
            else              v = make_float4(0.f, 0.f, 0.f, 0.f);
            if (use_act) {
                float4 sc = *(const float4*)(scale + c);
                float4 sf = *(const float4*)(shift + c);
                v.x = fmaxf(fmaf(v.x, sc.x, sf.x), 0.f);
                v.y = fmaxf(fmaf(v.y, sc.y, sf.y), 0.f);
                v.z = fmaxf(fmaf(v.z, sc.z, sf.z), 0.f);
                v.w = fmaxf(fmaf(v.w, sc.w, sf.w), 0.f);
            }
            __nv_bfloat162 h01 = __floats2bfloat162_rn(v.x, v.y);
            __nv_bfloat162 h23 = __floats2bfloat162_rn(v.z, v.w);
            float2 hf01 = __bfloat1622float2(h01);
            float2 hf23 = __bfloat1622float2(h23);
            __nv_bfloat162 l01 = __floats2bfloat162_rn(v.x - hf01.x, v.y - hf01.y);
            __nv_bfloat162 l23 = __floats2bfloat162_rn(v.z - hf23.x, v.w - hf23.y);
            uint32_t w0 = (uint32_t)(r * SA_W + (c >> 1));   // word index, 8B aligned
            uint2 hh; hh.x = *(uint32_t*)&h01; hh.y = *(uint32_t*)&h23;
            uint2 ll; ll.x = *(uint32_t*)&l01; ll.y = *(uint32_t*)&l23;
            *(uint2*)(sm + SM_AHI + w0 * 4) = hh;
            *(uint2*)(sm + SM_ALO + w0 * 4) = ll;
        }
    }
    __syncthreads();

    const uint32_t* pAh = (const uint32_t*)(sm + SM_AHI);
    const uint32_t* pAl = (const uint32_t*)(sm + SM_ALO);
    const uint32_t* pBh = (const uint32_t*)(sm + SM_WHI);
    const uint32_t* pBl = (const uint32_t*)(sm + SM_WLO);

    int m0 = (wid & 3) * 16;      // row strip
    int n0 = (wid >> 2) * 64;     // col half
    int g = lane >> 2, q = lane & 3;

    float acc[8][4] = {};
#pragma unroll
    for (int k = 0; k < 8; k++) {
        int kb2 = k * 8;          // k*16 elems = 8 words
        int ai = (m0 + g) * SA_W + kb2 + q;
        uint32_t ah0 = pAh[ai],           ah1 = pAh[ai + 8 * SA_W];
        uint32_t ah2 = pAh[ai + 4],       ah3 = pAh[ai + 8 * SA_W + 4];
        uint32_t al0 = pAl[ai],           al1 = pAl[ai + 8 * SA_W];
        uint32_t al2 = pAl[ai + 4],       al3 = pAl[ai + 8 * SA_W + 4];
#pragma unroll
        for (int t = 0; t < 8; t++) {
            int bi = (n0 + t * 8 + g) * SA_W + kb2 + q;
            uint32_t bh0 = pBh[bi], bh1 = pBh[bi + 4];
            uint32_t bl0 = pBl[bi], bl1 = pBl[bi + 4];
            mma_bf16(acc[t], ah0, ah1, ah2, ah3, bh0, bh1);
            mma_bf16(acc[t], al0, al1, al2, al3, bh0, bh1);
            mma_bf16(acc[t], ah0, ah1, ah2, ah3, bl0, bl1);
        }
    }

    // epilogue: write fp16; c0,c1 -> row m0+g ; c2,c3 -> row m0+g+8
    int r0g = row0 + m0 + g;
#pragma unroll
    for (int t = 0; t < 8; t++) {
        int colp = n0 + t * 8 + q * 2;
        float2 bv = *(const float2*)(bias + colp);
        if (r0g < N) {
            __half2 o = __floats2half2_rn(acc[t][0] + bv.x, acc[t][1] + bv.y);
            *(__half2*)(out + (size_t)r0g * D + colp) = o;
        }
        if (r0g + 8 < N) {
            __half2 o = __floats2half2_rn(acc[t][2] + bv.x, acc[t][3] + bv.y);
            *(__half2*)(out + (size_t)(r0g + 8) * D + colp) = o;
        }
    }
}

// ---------------- CSR build ----------------
__global__ void hist_kernel(const int* __restrict__ row, int* __restrict__ deg, int E)
{
    int e = blockIdx.x * blockDim.x + threadIdx.x;
    if (e < E) atomicAdd(&deg[row[e]], 1);
}

__global__ __launch_bounds__(1024) void blocksum_kernel(
    const int* __restrict__ deg, int* __restrict__ blksum, int N)
{
    int i = blockIdx.x * 1024 + threadIdx.x;
    int v = (i < N) ? deg[i] : 0;
#pragma unroll
    for (int off = 16; off > 0; off >>= 1) v += __shfl_down_sync(0xffffffffu, v, off);
    __shared__ int smr[32];
    int lane = threadIdx.x & 31, wid = threadIdx.x >> 5;
    if (lane == 0) smr[wid] = v;
    __syncthreads();
    if (wid == 0) {
        v = smr[lane];
#pragma unroll
        for (int off = 16; off > 0; off >>= 1) v += __shfl_down_sync(0xffffffffu, v, off);
        if (lane == 0) blksum[blockIdx.x] = v;
    }
}

__global__ __launch_bounds__(1024) void scanpart_kernel(int* __restrict__ blksum, int nb)
{
    __shared__ int smr[1024];
    int tid = threadIdx.x;
    smr[tid] = (tid < nb) ? blksum[tid] : 0;
    __syncthreads();
    if (tid == 0) {
        int run = 0;
        for (int i = 0; i < nb; i++) { int t = smr[i]; smr[i] = run; run += t; }
    }
    __syncthreads();
    if (tid < nb) blksum[tid] = smr[tid];
}

__global__ __launch_bounds__(1024) void rowptr_kernel(
    const int* __restrict__ deg, const int* __restrict__ blksum,
    int* __restrict__ rowptr, int N)
{
    int i = blockIdx.x * 1024 + threadIdx.x;
    int v = (i < N) ? deg[i] : 0;
    int lane = threadIdx.x & 31, wid = threadIdx.x >> 5;
    int incl = v;
#pragma unroll
    for (int off = 1; off < 32; off <<= 1) {
        int t = __shfl_up_sync(0xffffffffu, incl, off);
        if (lane >= off) incl += t;
    }
    __shared__ int wsum[32];
    if (lane == 31) wsum[wid] = incl;
    __syncthreads();
    if (wid == 0) {
        int w = wsum[lane];
#pragma unroll
        for (int off = 1; off < 32; off <<= 1) {
            int t = __shfl_up_sync(0xffffffffu, w, off);
            if (lane >= off) w += t;
        }
        wsum[lane] = w;
    }
    __syncthreads();
    int offset = blksum[blockIdx.x] + (wid > 0 ? wsum[wid - 1] : 0);
    int excl = offset + incl - v;
    if (i < N) rowptr[i] = excl;
    if (i == N - 1) rowptr[N] = excl + v;
}

__global__ void scatter_kernel(
    const int* __restrict__ row, const int* __restrict__ col,
    const float* __restrict__ ew, int* __restrict__ cursor,
    int* __restrict__ ecol, float* __restrict__ ew2, int E)
{
    int e = blockIdx.x * blockDim.x + threadIdx.x;
    if (e < E) {
        int p = atomicAdd(&cursor[row[e]], 1);
        ecol[p] = col[e];
        ew2[p]  = ew[e];
    }
}

// ---------------- gather SpMM (fp16 in, fp32 out): one warp per row ----------------
__global__ __launch_bounds__(256) void spmm_csr_kernel(
    const __half* __restrict__ H, const int* __restrict__ rowptr,
    const int* __restrict__ ecol, const float* __restrict__ ew2,
    float* __restrict__ out, int N)
{
    int r = blockIdx.x * 8 + (threadIdx.x >> 5);
    if (r >= N) return;
    int lane = threadIdx.x & 31;
    int start = rowptr[r], end = rowptr[r + 1];

    float4 acc = make_float4(0.f, 0.f, 0.f, 0.f);
    const uint2* Hv = (const uint2*)H;    // 32 x uint2 per row (4 halfs each)

    for (int base = start; base < end; base += 32) {
        int e = base + lane;
        int c = 0; float w = 0.f;
        if (e < end) { c = ecol[e]; w = ew2[e]; }
        int cnt = min(32, end - base);
#pragma unroll 4
        for (int i = 0; i < cnt; i++) {
            int ci  = __shfl_sync(0xffffffffu, c, i);
            float wi = __shfl_sync(0xffffffffu, w, i);
            uint2 pv = Hv[(size_t)ci * 32 + lane];
            float2 v01 = __half22float2(*(__half2*)&pv.x);
            float2 v23 = __half22float2(*(__half2*)&pv.y);
            acc.x = fmaf(wi, v01.x, acc.x);
            acc.y = fmaf(wi, v01.y, acc.y);
            acc.z = fmaf(wi, v23.x, acc.z);
            acc.w = fmaf(wi, v23.y, acc.w);
        }
    }
    ((float4*)(out + (size_t)r * D))[lane] = acc;
}

// ---------------- BN ----------------
#define RPB 256
__global__ __launch_bounds__(128) void bn_stats_kernel(
    const float* __restrict__ A, float* __restrict__ sum,
    float* __restrict__ sumsq, int N)
{
    int d = threadIdx.x;
    int r0 = blockIdx.x * RPB;
    int rend = min(r0 + RPB, N);
    float s = 0.f, q = 0.f;
    for (int r = r0; r < rend; r++) {
        float v = A[(size_t)r * D + d];
        s += v;
        q = fmaf(v, v, q);
    }
    atomicAdd(&sum[d], s);
    atomicAdd(&sumsq[d], q);
}

__global__ void bn_finalize_kernel(
    const float* __restrict__ sum, const float* __restrict__ sumsq,
    const float* __restrict__ g, const float* __restrict__ be,
    float* __restrict__ scale, float* __restrict__ shift, float invN)
{
    int d = threadIdx.x;
    float m = sum[d] * invN;
    float v = sumsq[d] * invN - m * m;
    float sc = g[d] * rsqrtf(v + EPS);
    scale[d] = sc;
    shift[d] = be[d] - m * sc;
}

// ---------------------------------------------------------------------------
extern "C" void kernel_launch(void* const* d_in, const int* in_sizes, int n_in,
                              void* d_out, int out_size)
{
    const float* x   = (const float*)d_in[0];
    const float* ew  = (const float*)d_in[1];
    const float* W0  = (const float*)d_in[2];
    const float* b0  = (const float*)d_in[3];
    const float* g0  = (const float*)d_in[4];
    const float* be0 = (const float*)d_in[5];
    const float* W1  = (const float*)d_in[6];
    const float* b1  = (const float*)d_in[7];
    const float* g1  = (const float*)d_in[8];
    const float* be1 = (const float*)d_in[9];
    const float* W2  = (const float*)d_in[10];
    const float* b2  = (const float*)d_in[11];
    const int*   row = (const int*)d_in[12];
    const int*   col = (const int*)d_in[13];
    float* out = (float*)d_out;

    int N = in_sizes[0] / D;
    int E = in_sizes[1];

    float *A, *Sum, *Sumsq, *Scale, *Shift, *Ew2;
    __half* Z;
    int *Deg, *Rowptr, *Cursor, *Ecol, *Blksum;
    __nv_bfloat16 *Whi, *Wlo;
    cudaGetSymbolAddress((void**)&Z, g_Z);
    cudaGetSymbolAddress((void**)&A, g_A);
    cudaGetSymbolAddress((void**)&Sum, g_sum);
    cudaGetSymbolAddress((void**)&Sumsq, g_sumsq);
    cudaGetSymbolAddress((void**)&Scale, g_scale);
    cudaGetSymbolAddress((void**)&Shift, g_shift);
    cudaGetSymbolAddress((void**)&Deg, g_deg);
    cudaGetSymbolAddress((void**)&Rowptr, g_rowptr);
    cudaGetSymbolAddress((void**)&Cursor, g_cursor);
    cudaGetSymbolAddress((void**)&Ecol, g_ecol);
    cudaGetSymbolAddress((void**)&Ew2, g_ew2);
    cudaGetSymbolAddress((void**)&Blksum, g_blksum);
    cudaGetSymbolAddress((void**)&Whi, g_Whi);
    cudaGetSymbolAddress((void**)&Wlo, g_Wlo);

    cudaFuncSetAttribute(gemm_mma_kernel, cudaFuncAttributeMaxDynamicSharedMemorySize, SM_TOT);

    int gemmGrid  = (N + 63) / 64;
    int spmmGrid  = (N + 7) / 8;
    int statsGrid = (N + RPB - 1) / RPB;
    int nb        = (N + 1023) / 1024;
    float invN = 1.0f / (float)N;

    // ---- W prep + CSR build ----
    wprep_kernel<<<3, 256>>>(W0, W1, W2, Whi, Wlo);
    cudaMemsetAsync(Deg, 0, N * sizeof(int));
    hist_kernel<<<(E + 255) / 256, 256>>>(row, Deg, E);
    blocksum_kernel<<<nb, 1024>>>(Deg, Blksum, N);
    scanpart_kernel<<<1, 1024>>>(Blksum, nb);
    rowptr_kernel<<<nb, 1024>>>(Deg, Blksum, Rowptr, N);
    cudaMemcpyAsync(Cursor, Rowptr, N * sizeof(int), cudaMemcpyDeviceToDevice);
    scatter_kernel<<<(E + 255) / 256, 256>>>(row, col, ew, Cursor, Ecol, Ew2, E);

    // ---- layer 0 ----
    gemm_mma_kernel<<<gemmGrid, 256, SM_TOT>>>(x, Whi, Wlo, b0, nullptr, nullptr, Z, N, 0);
    spmm_csr_kernel<<<spmmGrid, 256>>>(Z, Rowptr, Ecol, Ew2, A, N);
    cudaMemsetAsync(Sum, 0, D * sizeof(float));
    cudaMemsetAsync(Sumsq, 0, D * sizeof(float));
    bn_stats_kernel<<<statsGrid, 128>>>(A, Sum, Sumsq, N);
    bn_finalize_kernel<<<1, 128>>>(Sum, Sumsq, g0, be0, Scale, Shift, invN);

    // ---- layer 1 ----
    gemm_mma_kernel<<<gemmGrid, 256, SM_TOT>>>(A, Whi + 128 * SA, Wlo + 128 * SA, b1,
                                               Scale, Shift, Z, N, 1);
    spmm_csr_kernel<<<spmmGrid, 256>>>(Z, Rowptr, Ecol, Ew2, A, N);
    cudaMemsetAsync(Sum, 0, D * sizeof(float));
    cudaMemsetAsync(Sumsq, 0, D * sizeof(float));
    bn_stats_kernel<<<statsGrid, 128>>>(A, Sum, Sumsq, N);
    bn_finalize_kernel<<<1, 128>>>(Sum, Sumsq, g1, be1, Scale, Shift, invN);

    // ---- layer 2 ----
    gemm_mma_kernel<<<gemmGrid, 256, SM_TOT>>>(A, Whi + 256 * SA, Wlo + 256 * SA, b2,
                                               Scale, Shift, Z, N, 1);
    spmm_csr_kernel<<<spmmGrid, 256>>>(Z, Rowptr, Ecol, Ew2, out, N);
}